// round 1
// baseline (speedup 1.0000x reference)
#include <cuda_runtime.h>

#define N0 4096
#define N1 8192
#define N2 4096

// Scratch (allocation-free: __device__ globals)
__device__ __align__(16) float g_x0[N0];
__device__ __align__(16) float g_x1[N1];
__device__ float g_sums0[8];
__device__ float g_sums1[8];

__device__ __forceinline__ float warp_sum(float v) {
#pragma unroll
    for (int o = 16; o > 0; o >>= 1) v += __shfl_xor_sync(0xffffffffu, v, o);
    return v;
}

// ---------------------------------------------------------------------------
// Phase A: x0 = tanh(inputs); 8 pre-side Hebbian reductions over layer 0.
// Single block, 1024 threads. Deterministic tree reduction.
// ---------------------------------------------------------------------------
__global__ void __launch_bounds__(1024) k_pre0(
    const float* __restrict__ in,
    const float* __restrict__ act,
    const float* __restrict__ a,
    const float* __restrict__ c,
    const float* __restrict__ d,
    const float* __restrict__ e)
{
    int tid = threadIdx.x;
    float s[8] = {0.f, 0.f, 0.f, 0.f, 0.f, 0.f, 0.f, 0.f};
    for (int i = tid; i < N0; i += 1024) {
        float x = tanhf(in[i]);
        g_x0[i] = x;
        float ev = e[i];
        float av = a[i] * act[i];
        float cv = c[i] * act[i];
        float dv = d[i];
        s[0] += ev * av * x;  s[1] += ev * x;
        s[2] += ev * cv * x;  s[3] += ev * dv * x;
        s[4] += av * x;       s[5] += x;
        s[6] += cv * x;       s[7] += dv * x;
    }
    __shared__ float sh[8][32];
#pragma unroll
    for (int k = 0; k < 8; k++) s[k] = warp_sum(s[k]);
    int w = tid >> 5, l = tid & 31;
    if (l == 0) {
#pragma unroll
        for (int k = 0; k < 8; k++) sh[k][w] = s[k];
    }
    __syncthreads();
    if (tid < 256) {
        int k = tid >> 5, ln = tid & 31;
        float v = warp_sum(sh[k][ln]);
        if (ln == 0) g_sums0[k] = v;
    }
}

// ---------------------------------------------------------------------------
// Phase C: 8 pre-side reductions over layer 1 (x1 already computed).
// ---------------------------------------------------------------------------
__global__ void __launch_bounds__(1024) k_pre1(
    const float* __restrict__ act,
    const float* __restrict__ a,
    const float* __restrict__ c,
    const float* __restrict__ d,
    const float* __restrict__ e)
{
    int tid = threadIdx.x;
    float s[8] = {0.f, 0.f, 0.f, 0.f, 0.f, 0.f, 0.f, 0.f};
    for (int i = tid; i < N1; i += 1024) {
        float x = g_x1[i];
        float ev = e[i];
        float av = a[i] * act[i];
        float cv = c[i] * act[i];
        float dv = d[i];
        s[0] += ev * av * x;  s[1] += ev * x;
        s[2] += ev * cv * x;  s[3] += ev * dv * x;
        s[4] += av * x;       s[5] += x;
        s[6] += cv * x;       s[7] += dv * x;
    }
    __shared__ float sh[8][32];
#pragma unroll
    for (int k = 0; k < 8; k++) s[k] = warp_sum(s[k]);
    int w = tid >> 5, l = tid & 31;
    if (l == 0) {
#pragma unroll
        for (int k = 0; k < 8; k++) sh[k][w] = s[k];
    }
    __syncthreads();
    if (tid < 256) {
        int k = tid >> 5, ln = tid & 31;
        float v = warp_sum(sh[k][ln]);
        if (ln == 0) g_sums1[k] = v;
    }
}

// ---------------------------------------------------------------------------
// GEMV with fused Hebbian epilogue. One warp per row, float4 loads,
// x vector staged in shared memory. 8 rows per 256-thread block.
// ---------------------------------------------------------------------------
template <int NCOL4, bool APPLY_TANH>
__device__ __forceinline__ void gemv_body(
    const float* __restrict__ W,
    const float* __restrict__ xin,
    const float* __restrict__ act_post,
    const float* __restrict__ b_post,
    const float* __restrict__ c_post,
    const float* __restrict__ d_post,
    const float* __restrict__ e_post,
    const float* __restrict__ sums,
    float* __restrict__ out)
{
    __shared__ float4 sx[NCOL4];
    const float4* x4 = reinterpret_cast<const float4*>(xin);
    for (int i = threadIdx.x; i < NCOL4; i += 256) sx[i] = x4[i];
    __syncthreads();

    int warp = threadIdx.x >> 5;
    int lane = threadIdx.x & 31;
    int row = blockIdx.x * 8 + warp;

    const float4* Wr = reinterpret_cast<const float4*>(W) + (size_t)row * NCOL4;
    float acc = 0.f;
#pragma unroll 8
    for (int t = lane; t < NCOL4; t += 32) {
        float4 w  = Wr[t];
        float4 xv = sx[t];
        acc = fmaf(w.x, xv.x, acc);
        acc = fmaf(w.y, xv.y, acc);
        acc = fmaf(w.z, xv.z, acc);
        acc = fmaf(w.w, xv.w, acc);
    }
    acc = warp_sum(acc);

    if (lane == 0) {
        float P = b_post[row] * act_post[row];
        float C = c_post[row] * act_post[row];
        float D = d_post[row];
        float E = e_post[row];
        float h = 0.5f * (sums[0] + P * sums[1] + C * sums[2] + D * sums[3]
                 + E * (sums[4] + P * sums[5] + C * sums[6] + D * sums[7]));
        float y = acc + h;
        out[row] = APPLY_TANH ? tanhf(y) : y;
    }
}

__global__ void __launch_bounds__(256) k_gemv0(
    const float* __restrict__ W0,
    const float* __restrict__ act1,
    const float* __restrict__ b1,
    const float* __restrict__ c1,
    const float* __restrict__ d1,
    const float* __restrict__ e1)
{
    gemv_body<N0 / 4, true>(W0, g_x0, act1, b1, c1, d1, e1, g_sums0, g_x1);
}

__global__ void __launch_bounds__(256) k_gemv1(
    const float* __restrict__ W1,
    const float* __restrict__ act2,
    const float* __restrict__ b2,
    const float* __restrict__ c2,
    const float* __restrict__ d2,
    const float* __restrict__ e2,
    float* __restrict__ out)
{
    gemv_body<N1 / 4, false>(W1, g_x1, act2, b2, c2, d2, e2, g_sums1, out);
}

// ---------------------------------------------------------------------------
// Launch
// ---------------------------------------------------------------------------
extern "C" void kernel_launch(void* const* d_in, const int* in_sizes, int n_in,
                              void* d_out, int out_size)
{
    const float* inputs = (const float*)d_in[0];
    const float* act0   = (const float*)d_in[1];
    const float* act1   = (const float*)d_in[2];
    const float* act2   = (const float*)d_in[3];
    const float* W0     = (const float*)d_in[4];
    const float* W1     = (const float*)d_in[5];
    const float* a0     = (const float*)d_in[6];
    const float* c0     = (const float*)d_in[7];
    const float* d0     = (const float*)d_in[8];
    const float* e0     = (const float*)d_in[9];
    const float* a1     = (const float*)d_in[10];
    const float* b1     = (const float*)d_in[11];
    const float* c1     = (const float*)d_in[12];
    const float* d1     = (const float*)d_in[13];
    const float* e1     = (const float*)d_in[14];
    const float* b2     = (const float*)d_in[15];
    const float* c2     = (const float*)d_in[16];
    const float* d2     = (const float*)d_in[17];
    const float* e2     = (const float*)d_in[18];
    float* out = (float*)d_out;

    k_pre0<<<1, 1024>>>(inputs, act0, a0, c0, d0, e0);
    k_gemv0<<<N1 / 8, 256>>>(W0, act1, b1, c1, d1, e1);
    k_pre1<<<1, 1024>>>(act1, a1, c1, d1, e1);
    k_gemv1<<<N2 / 8, 256>>>(W1, act2, b2, c2, d2, e2, out);
}

// round 2
// speedup vs baseline: 1.1567x; 1.1567x over previous
#include <cuda_runtime.h>

#define N0 4096
#define N1 8192
#define N2 4096

// Scratch (allocation-free: __device__ globals)
__device__ __align__(16) float g_x0[N0];
__device__ __align__(16) float g_x1[N1];
__device__ float g_sums0[8];
__device__ float g_sums1[8];

__device__ __forceinline__ float warp_sum(float v) {
#pragma unroll
    for (int o = 16; o > 0; o >>= 1) v += __shfl_xor_sync(0xffffffffu, v, o);
    return v;
}

// ---------------------------------------------------------------------------
// Phase A: x0 = tanh(inputs); 8 pre-side Hebbian reductions over layer 0.
// ---------------------------------------------------------------------------
__global__ void __launch_bounds__(1024) k_pre0(
    const float* __restrict__ in,
    const float* __restrict__ act,
    const float* __restrict__ a,
    const float* __restrict__ c,
    const float* __restrict__ d,
    const float* __restrict__ e)
{
    int tid = threadIdx.x;
    float s[8] = {0.f, 0.f, 0.f, 0.f, 0.f, 0.f, 0.f, 0.f};
    for (int i = tid; i < N0; i += 1024) {
        float x = tanhf(in[i]);
        g_x0[i] = x;
        float ev = e[i];
        float av = a[i] * act[i];
        float cv = c[i] * act[i];
        float dv = d[i];
        s[0] += ev * av * x;  s[1] += ev * x;
        s[2] += ev * cv * x;  s[3] += ev * dv * x;
        s[4] += av * x;       s[5] += x;
        s[6] += cv * x;       s[7] += dv * x;
    }
    __shared__ float sh[8][32];
#pragma unroll
    for (int k = 0; k < 8; k++) s[k] = warp_sum(s[k]);
    int w = tid >> 5, l = tid & 31;
    if (l == 0) {
#pragma unroll
        for (int k = 0; k < 8; k++) sh[k][w] = s[k];
    }
    __syncthreads();
    if (tid < 256) {
        int k = tid >> 5, ln = tid & 31;
        float v = warp_sum(sh[k][ln]);
        if (ln == 0) g_sums0[k] = v;
    }
}

// ---------------------------------------------------------------------------
// Phase C: 8 pre-side reductions over layer 1 (x1 already computed).
// ---------------------------------------------------------------------------
__global__ void __launch_bounds__(1024) k_pre1(
    const float* __restrict__ act,
    const float* __restrict__ a,
    const float* __restrict__ c,
    const float* __restrict__ d,
    const float* __restrict__ e)
{
    int tid = threadIdx.x;
    float s[8] = {0.f, 0.f, 0.f, 0.f, 0.f, 0.f, 0.f, 0.f};
    for (int i = tid; i < N1; i += 1024) {
        float x = g_x1[i];
        float ev = e[i];
        float av = a[i] * act[i];
        float cv = c[i] * act[i];
        float dv = d[i];
        s[0] += ev * av * x;  s[1] += ev * x;
        s[2] += ev * cv * x;  s[3] += ev * dv * x;
        s[4] += av * x;       s[5] += x;
        s[6] += cv * x;       s[7] += dv * x;
    }
    __shared__ float sh[8][32];
#pragma unroll
    for (int k = 0; k < 8; k++) s[k] = warp_sum(s[k]);
    int w = tid >> 5, l = tid & 31;
    if (l == 0) {
#pragma unroll
        for (int k = 0; k < 8; k++) sh[k][w] = s[k];
    }
    __syncthreads();
    if (tid < 256) {
        int k = tid >> 5, ln = tid & 31;
        float v = warp_sum(sh[k][ln]);
        if (ln == 0) g_sums1[k] = v;
    }
}

// ---------------------------------------------------------------------------
// Hebbian epilogue scalar for one output row.
// ---------------------------------------------------------------------------
__device__ __forceinline__ float heb_row(
    int row,
    const float* __restrict__ act_post,
    const float* __restrict__ b_post,
    const float* __restrict__ c_post,
    const float* __restrict__ d_post,
    const float* __restrict__ e_post,
    const float* __restrict__ sums)
{
    float P = b_post[row] * act_post[row];
    float C = c_post[row] * act_post[row];
    float D = d_post[row];
    float E = e_post[row];
    return 0.5f * (sums[0] + P * sums[1] + C * sums[2] + D * sums[3]
          + E * (sums[4] + P * sums[5] + C * sums[6] + D * sums[7]));
}

// ---------------------------------------------------------------------------
// GEMV0: W0[8192 x 4096] @ x0, +hebbian, tanh -> g_x1.
// 128 blocks x 1024 threads (single wave). 32 warps/block, 2 rows/warp.
// ---------------------------------------------------------------------------
__global__ void __launch_bounds__(1024) k_gemv0(
    const float* __restrict__ W0,
    const float* __restrict__ act1,
    const float* __restrict__ b1,
    const float* __restrict__ c1,
    const float* __restrict__ d1,
    const float* __restrict__ e1)
{
    constexpr int NCOL4 = N0 / 4;       // 1024 float4 per row
    constexpr int LPT = NCOL4 / 32;     // 32 float4 per lane per row
    __shared__ float4 sx[NCOL4];        // 16 KB

    const float4* x4 = reinterpret_cast<const float4*>(g_x0);
    for (int i = threadIdx.x; i < NCOL4; i += 1024) sx[i] = x4[i];
    __syncthreads();

    int warp = threadIdx.x >> 5;
    int lane = threadIdx.x & 31;
    int r0 = blockIdx.x * 64 + warp;    // rows r0 and r0+32
    int r1 = r0 + 32;

    const float4* Wr0 = reinterpret_cast<const float4*>(W0) + (size_t)r0 * NCOL4 + lane;
    const float4* Wr1 = reinterpret_cast<const float4*>(W0) + (size_t)r1 * NCOL4 + lane;

    float4 acc0 = make_float4(0.f, 0.f, 0.f, 0.f);
    float4 acc1 = make_float4(0.f, 0.f, 0.f, 0.f);
#pragma unroll 8
    for (int t = 0; t < LPT; t++) {
        float4 w0 = __ldcs(Wr0 + t * 32);
        float4 w1 = __ldcs(Wr1 + t * 32);
        float4 xv = sx[t * 32 + lane];
        acc0.x = fmaf(w0.x, xv.x, acc0.x);
        acc0.y = fmaf(w0.y, xv.y, acc0.y);
        acc0.z = fmaf(w0.z, xv.z, acc0.z);
        acc0.w = fmaf(w0.w, xv.w, acc0.w);
        acc1.x = fmaf(w1.x, xv.x, acc1.x);
        acc1.y = fmaf(w1.y, xv.y, acc1.y);
        acc1.z = fmaf(w1.z, xv.z, acc1.z);
        acc1.w = fmaf(w1.w, xv.w, acc1.w);
    }
    float s0 = warp_sum((acc0.x + acc0.y) + (acc0.z + acc0.w));
    float s1 = warp_sum((acc1.x + acc1.y) + (acc1.z + acc1.w));

    if (lane == 0) {
        g_x1[r0] = tanhf(s0 + heb_row(r0, act1, b1, c1, d1, e1, g_sums0));
        g_x1[r1] = tanhf(s1 + heb_row(r1, act1, b1, c1, d1, e1, g_sums0));
    }
}

// ---------------------------------------------------------------------------
// GEMV1: W1[4096 x 8192] @ x1, +hebbian -> out.
// 128 blocks x 1024 threads (single wave). 32 warps/block, 1 row/warp.
// ---------------------------------------------------------------------------
__global__ void __launch_bounds__(1024) k_gemv1(
    const float* __restrict__ W1,
    const float* __restrict__ act2,
    const float* __restrict__ b2,
    const float* __restrict__ c2,
    const float* __restrict__ d2,
    const float* __restrict__ e2,
    float* __restrict__ out)
{
    constexpr int NCOL4 = N1 / 4;       // 2048 float4 per row
    constexpr int LPT = NCOL4 / 32;     // 64 float4 per lane
    __shared__ float4 sx[NCOL4];        // 32 KB

    const float4* x4 = reinterpret_cast<const float4*>(g_x1);
    for (int i = threadIdx.x; i < NCOL4; i += 1024) sx[i] = x4[i];
    __syncthreads();

    int warp = threadIdx.x >> 5;
    int lane = threadIdx.x & 31;
    int row = blockIdx.x * 32 + warp;

    const float4* Wr = reinterpret_cast<const float4*>(W1) + (size_t)row * NCOL4 + lane;

    float4 accA = make_float4(0.f, 0.f, 0.f, 0.f);
    float4 accB = make_float4(0.f, 0.f, 0.f, 0.f);
#pragma unroll 8
    for (int t = 0; t < LPT; t += 2) {
        float4 wA = __ldcs(Wr + t * 32);
        float4 wB = __ldcs(Wr + (t + 1) * 32);
        float4 xA = sx[t * 32 + lane];
        float4 xB = sx[(t + 1) * 32 + lane];
        accA.x = fmaf(wA.x, xA.x, accA.x);
        accA.y = fmaf(wA.y, xA.y, accA.y);
        accA.z = fmaf(wA.z, xA.z, accA.z);
        accA.w = fmaf(wA.w, xA.w, accA.w);
        accB.x = fmaf(wB.x, xB.x, accB.x);
        accB.y = fmaf(wB.y, xB.y, accB.y);
        accB.z = fmaf(wB.z, xB.z, accB.z);
        accB.w = fmaf(wB.w, xB.w, accB.w);
    }
    float s = warp_sum(((accA.x + accA.y) + (accA.z + accA.w))
                     + ((accB.x + accB.y) + (accB.z + accB.w)));

    if (lane == 0) {
        out[row] = s + heb_row(row, act2, b2, c2, d2, e2, g_sums1);
    }
}

// ---------------------------------------------------------------------------
// Launch
// ---------------------------------------------------------------------------
extern "C" void kernel_launch(void* const* d_in, const int* in_sizes, int n_in,
                              void* d_out, int out_size)
{
    const float* inputs = (const float*)d_in[0];
    const float* act0   = (const float*)d_in[1];
    const float* act1   = (const float*)d_in[2];
    const float* act2   = (const float*)d_in[3];
    const float* W0     = (const float*)d_in[4];
    const float* W1     = (const float*)d_in[5];
    const float* a0     = (const float*)d_in[6];
    const float* c0     = (const float*)d_in[7];
    const float* d0     = (const float*)d_in[8];
    const float* e0     = (const float*)d_in[9];
    const float* a1     = (const float*)d_in[10];
    const float* b1     = (const float*)d_in[11];
    const float* c1     = (const float*)d_in[12];
    const float* d1     = (const float*)d_in[13];
    const float* e1     = (const float*)d_in[14];
    const float* b2     = (const float*)d_in[15];
    const float* c2     = (const float*)d_in[16];
    const float* d2     = (const float*)d_in[17];
    const float* e2     = (const float*)d_in[18];
    float* out = (float*)d_out;

    k_pre0<<<1, 1024>>>(inputs, act0, a0, c0, d0, e0);
    k_gemv0<<<128, 1024>>>(W0, act1, b1, c1, d1, e1);
    k_pre1<<<1, 1024>>>(act1, a1, c1, d1, e1);
    k_gemv1<<<128, 1024>>>(W1, act2, b2, c2, d2, e2, out);
}

// round 3
// speedup vs baseline: 1.1809x; 1.0209x over previous
#include <cuda_runtime.h>

#define N0 4096
#define N1 8192
#define N2 4096

// Scratch (allocation-free: __device__ globals)
__device__ __align__(16) float g_x1[N1];

__device__ __forceinline__ float warp_sum(float v) {
#pragma unroll
    for (int o = 16; o > 0; o >>= 1) v += __shfl_xor_sync(0xffffffffu, v, o);
    return v;
}

// Block-wide reduction of 8 partial sums (1024 threads). Deterministic.
// Results land in s_sums[0..7] (smem). Caller must __syncthreads() after.
__device__ __forceinline__ void block_reduce8(float s[8], float (*sh)[32], float* s_sums)
{
    int tid = threadIdx.x;
    int w = tid >> 5, l = tid & 31;
#pragma unroll
    for (int k = 0; k < 8; k++) s[k] = warp_sum(s[k]);
    if (l == 0) {
#pragma unroll
        for (int k = 0; k < 8; k++) sh[k][w] = s[k];
    }
    __syncthreads();
    if (tid < 256) {
        int k = tid >> 5, ln = tid & 31;
        float v = warp_sum(sh[k][ln]);
        if (ln == 0) s_sums[k] = v;
    }
}

// Hebbian epilogue scalar for one output row, sums in smem.
__device__ __forceinline__ float heb_row(
    int row,
    const float* __restrict__ act_post,
    const float* __restrict__ b_post,
    const float* __restrict__ c_post,
    const float* __restrict__ d_post,
    const float* __restrict__ e_post,
    const float* __restrict__ sums)
{
    float P = b_post[row] * act_post[row];
    float C = c_post[row] * act_post[row];
    float D = d_post[row];
    float E = e_post[row];
    return 0.5f * (sums[0] + P * sums[1] + C * sums[2] + D * sums[3]
          + E * (sums[4] + P * sums[5] + C * sums[6] + D * sums[7]));
}

// Accumulate the 8 Hebbian pre-side partial sums for a float4 of (x, act, a, c, d, e).
__device__ __forceinline__ void heb_partial4(
    float s[8], float4 xv, float4 actv, float4 av, float4 cv, float4 dv, float4 ev)
{
    float xs[4]  = {xv.x, xv.y, xv.z, xv.w};
    float acs[4] = {actv.x, actv.y, actv.z, actv.w};
    float as[4]  = {av.x, av.y, av.z, av.w};
    float cs[4]  = {cv.x, cv.y, cv.z, cv.w};
    float ds[4]  = {dv.x, dv.y, dv.z, dv.w};
    float es[4]  = {ev.x, ev.y, ev.z, ev.w};
#pragma unroll
    for (int j = 0; j < 4; j++) {
        float x = xs[j];
        float e = es[j];
        float p = as[j] * acs[j];
        float c = cs[j] * acs[j];
        float d = ds[j];
        s[0] += e * p * x;  s[1] += e * x;
        s[2] += e * c * x;  s[3] += e * d * x;
        s[4] += p * x;      s[5] += x;
        s[6] += c * x;      s[7] += d * x;
    }
}

// ---------------------------------------------------------------------------
// GEMV0 (fused): x0 = tanh(inputs); sums0 over layer 0; W0 @ x0 + heb, tanh -> g_x1
// 128 blocks x 1024 threads. 32 warps/block, 2 rows/warp (rows r, r+32).
// ---------------------------------------------------------------------------
__global__ void __launch_bounds__(1024) k_gemv0(
    const float* __restrict__ W0,
    const float* __restrict__ inputs,
    const float* __restrict__ act0,
    const float* __restrict__ a0,
    const float* __restrict__ c0,
    const float* __restrict__ d0,
    const float* __restrict__ e0,
    const float* __restrict__ act1,
    const float* __restrict__ b1,
    const float* __restrict__ c1,
    const float* __restrict__ d1,
    const float* __restrict__ e1)
{
    constexpr int NCOL4 = N0 / 4;       // 1024 float4 per row
    __shared__ float4 sx[NCOL4];        // 16 KB
    __shared__ float sh[8][32];
    __shared__ float s_sums[8];

    int tid = threadIdx.x;

    // Phase 1: x0 = tanh(inputs) into smem; Hebbian pre-side partial sums.
    {
        float s[8] = {0.f, 0.f, 0.f, 0.f, 0.f, 0.f, 0.f, 0.f};
        // exactly one float4 per thread (NCOL4 == 1024)
        float4 iv = reinterpret_cast<const float4*>(inputs)[tid];
        float4 xv = make_float4(tanhf(iv.x), tanhf(iv.y), tanhf(iv.z), tanhf(iv.w));
        sx[tid] = xv;
        float4 actv = reinterpret_cast<const float4*>(act0)[tid];
        float4 av   = reinterpret_cast<const float4*>(a0)[tid];
        float4 cv   = reinterpret_cast<const float4*>(c0)[tid];
        float4 dv   = reinterpret_cast<const float4*>(d0)[tid];
        float4 ev   = reinterpret_cast<const float4*>(e0)[tid];
        heb_partial4(s, xv, actv, av, cv, dv, ev);
        block_reduce8(s, sh, s_sums);
    }
    __syncthreads();

    // Phase 2: GEMV mainloop, 2 rows/warp, MLP=8 front-batched loads.
    int warp = tid >> 5;
    int lane = tid & 31;
    int r0 = blockIdx.x * 64 + warp;    // rows r0 and r0+32
    int r1 = r0 + 32;

    const float4* Wr0 = reinterpret_cast<const float4*>(W0) + (size_t)r0 * NCOL4 + lane;
    const float4* Wr1 = reinterpret_cast<const float4*>(W0) + (size_t)r1 * NCOL4 + lane;

    float4 acc0 = make_float4(0.f, 0.f, 0.f, 0.f);
    float4 acc1 = make_float4(0.f, 0.f, 0.f, 0.f);
#pragma unroll 1
    for (int t = 0; t < 32; t += 4) {
        float4 w0[4], w1[4];
#pragma unroll
        for (int j = 0; j < 4; j++) w0[j] = __ldcs(Wr0 + (t + j) * 32);
#pragma unroll
        for (int j = 0; j < 4; j++) w1[j] = __ldcs(Wr1 + (t + j) * 32);
#pragma unroll
        for (int j = 0; j < 4; j++) {
            float4 xv = sx[(t + j) * 32 + lane];
            acc0.x = fmaf(w0[j].x, xv.x, acc0.x);
            acc0.y = fmaf(w0[j].y, xv.y, acc0.y);
            acc0.z = fmaf(w0[j].z, xv.z, acc0.z);
            acc0.w = fmaf(w0[j].w, xv.w, acc0.w);
            acc1.x = fmaf(w1[j].x, xv.x, acc1.x);
            acc1.y = fmaf(w1[j].y, xv.y, acc1.y);
            acc1.z = fmaf(w1[j].z, xv.z, acc1.z);
            acc1.w = fmaf(w1[j].w, xv.w, acc1.w);
        }
    }
    float s0 = warp_sum((acc0.x + acc0.y) + (acc0.z + acc0.w));
    float s1 = warp_sum((acc1.x + acc1.y) + (acc1.z + acc1.w));

    if (lane == 0) {
        g_x1[r0] = tanhf(s0 + heb_row(r0, act1, b1, c1, d1, e1, s_sums));
        g_x1[r1] = tanhf(s1 + heb_row(r1, act1, b1, c1, d1, e1, s_sums));
    }
}

// ---------------------------------------------------------------------------
// GEMV1 (fused): sums1 over layer 1 (from g_x1); W1 @ x1 + heb -> out
// 128 blocks x 1024 threads. 32 warps/block, 1 row/warp, MLP=8.
// ---------------------------------------------------------------------------
__global__ void __launch_bounds__(1024) k_gemv1(
    const float* __restrict__ W1,
    const float* __restrict__ act1,
    const float* __restrict__ a1,
    const float* __restrict__ c1,
    const float* __restrict__ d1,
    const float* __restrict__ e1,
    const float* __restrict__ act2,
    const float* __restrict__ b2,
    const float* __restrict__ c2,
    const float* __restrict__ d2,
    const float* __restrict__ e2,
    float* __restrict__ out)
{
    constexpr int NCOL4 = N1 / 4;       // 2048 float4 per row
    __shared__ float4 sx[NCOL4];        // 32 KB
    __shared__ float sh[8][32];
    __shared__ float s_sums[8];

    int tid = threadIdx.x;

    // Phase 1: stage x1 into smem; Hebbian pre-side partial sums (2 float4/thread).
    {
        float s[8] = {0.f, 0.f, 0.f, 0.f, 0.f, 0.f, 0.f, 0.f};
        const float4* x4 = reinterpret_cast<const float4*>(g_x1);
#pragma unroll
        for (int rpt = 0; rpt < 2; rpt++) {
            int i = tid + rpt * 1024;
            float4 xv = x4[i];
            sx[i] = xv;
            float4 actv = reinterpret_cast<const float4*>(act1)[i];
            float4 av   = reinterpret_cast<const float4*>(a1)[i];
            float4 cv   = reinterpret_cast<const float4*>(c1)[i];
            float4 dv   = reinterpret_cast<const float4*>(d1)[i];
            float4 ev   = reinterpret_cast<const float4*>(e1)[i];
            heb_partial4(s, xv, actv, av, cv, dv, ev);
        }
        block_reduce8(s, sh, s_sums);
    }
    __syncthreads();

    // Phase 2: GEMV mainloop, 1 row/warp, MLP=8 front-batched loads.
    int warp = tid >> 5;
    int lane = tid & 31;
    int row = blockIdx.x * 32 + warp;

    const float4* Wr = reinterpret_cast<const float4*>(W1) + (size_t)row * NCOL4 + lane;

    float4 acc0 = make_float4(0.f, 0.f, 0.f, 0.f);
    float4 acc1 = make_float4(0.f, 0.f, 0.f, 0.f);
#pragma unroll 1
    for (int t = 0; t < 64; t += 8) {
        float4 w[8];
#pragma unroll
        for (int j = 0; j < 8; j++) w[j] = __ldcs(Wr + (t + j) * 32);
#pragma unroll
        for (int j = 0; j < 8; j++) {
            float4 xv = sx[(t + j) * 32 + lane];
            if (j & 1) {
                acc1.x = fmaf(w[j].x, xv.x, acc1.x);
                acc1.y = fmaf(w[j].y, xv.y, acc1.y);
                acc1.z = fmaf(w[j].z, xv.z, acc1.z);
                acc1.w = fmaf(w[j].w, xv.w, acc1.w);
            } else {
                acc0.x = fmaf(w[j].x, xv.x, acc0.x);
                acc0.y = fmaf(w[j].y, xv.y, acc0.y);
                acc0.z = fmaf(w[j].z, xv.z, acc0.z);
                acc0.w = fmaf(w[j].w, xv.w, acc0.w);
            }
        }
    }
    float s = warp_sum(((acc0.x + acc0.y) + (acc0.z + acc0.w))
                     + ((acc1.x + acc1.y) + (acc1.z + acc1.w)));

    if (lane == 0) {
        out[row] = s + heb_row(row, act2, b2, c2, d2, e2, s_sums);
    }
}

// ---------------------------------------------------------------------------
// Launch
// ---------------------------------------------------------------------------
extern "C" void kernel_launch(void* const* d_in, const int* in_sizes, int n_in,
                              void* d_out, int out_size)
{
    const float* inputs = (const float*)d_in[0];
    const float* act0   = (const float*)d_in[1];
    const float* act1   = (const float*)d_in[2];
    const float* act2   = (const float*)d_in[3];
    const float* W0     = (const float*)d_in[4];
    const float* W1     = (const float*)d_in[5];
    const float* a0     = (const float*)d_in[6];
    const float* c0     = (const float*)d_in[7];
    const float* d0     = (const float*)d_in[8];
    const float* e0     = (const float*)d_in[9];
    const float* a1     = (const float*)d_in[10];
    const float* b1     = (const float*)d_in[11];
    const float* c1     = (const float*)d_in[12];
    const float* d1     = (const float*)d_in[13];
    const float* e1     = (const float*)d_in[14];
    const float* b2     = (const float*)d_in[15];
    const float* c2     = (const float*)d_in[16];
    const float* d2     = (const float*)d_in[17];
    const float* e2     = (const float*)d_in[18];
    float* out = (float*)d_out;

    k_gemv0<<<128, 1024>>>(W0, inputs, act0, a0, c0, d0, e0,
                           act1, b1, c1, d1, e1);
    k_gemv1<<<128, 1024>>>(W1, act1, a1, c1, d1, e1,
                           act2, b2, c2, d2, e2, out);
}

// round 4
// speedup vs baseline: 1.2653x; 1.0715x over previous
#include <cuda_runtime.h>

#define N0 4096
#define N1 8192
#define N2 4096
#define GRID 148

// Scratch (allocation-free: __device__ global)
__device__ __align__(16) float g_x1[N1];

__device__ __forceinline__ float warp_sum(float v) {
#pragma unroll
    for (int o = 16; o > 0; o >>= 1) v += __shfl_xor_sync(0xffffffffu, v, o);
    return v;
}

// Block-wide reduction of 8 partial sums (1024 threads). Deterministic.
__device__ __forceinline__ void block_reduce8(float s[8], float (*sh)[32], float* s_sums)
{
    int tid = threadIdx.x;
    int w = tid >> 5, l = tid & 31;
#pragma unroll
    for (int k = 0; k < 8; k++) s[k] = warp_sum(s[k]);
    if (l == 0) {
#pragma unroll
        for (int k = 0; k < 8; k++) sh[k][w] = s[k];
    }
    __syncthreads();
    if (tid < 256) {
        int k = tid >> 5, ln = tid & 31;
        float v = warp_sum(sh[k][ln]);
        if (ln == 0) s_sums[k] = v;
    }
}

__device__ __forceinline__ float heb_row_val(
    int row,
    const float* __restrict__ act_post,
    const float* __restrict__ b_post,
    const float* __restrict__ c_post,
    const float* __restrict__ d_post,
    const float* __restrict__ e_post,
    const float* __restrict__ sums)
{
    float P = b_post[row] * act_post[row];
    float C = c_post[row] * act_post[row];
    float D = d_post[row];
    float E = e_post[row];
    return 0.5f * (sums[0] + P * sums[1] + C * sums[2] + D * sums[3]
          + E * (sums[4] + P * sums[5] + C * sums[6] + D * sums[7]));
}

__device__ __forceinline__ void heb_partial4(
    float s[8], float4 xv, float4 actv, float4 av, float4 cv, float4 dv, float4 ev)
{
    float xs[4]  = {xv.x, xv.y, xv.z, xv.w};
    float acs[4] = {actv.x, actv.y, actv.z, actv.w};
    float as[4]  = {av.x, av.y, av.z, av.w};
    float cs[4]  = {cv.x, cv.y, cv.z, cv.w};
    float ds[4]  = {dv.x, dv.y, dv.z, dv.w};
    float es[4]  = {ev.x, ev.y, ev.z, ev.w};
#pragma unroll
    for (int j = 0; j < 4; j++) {
        float x = xs[j], e = es[j];
        float p = as[j] * acs[j];
        float c = cs[j] * acs[j];
        float d = ds[j];
        s[0] += e * p * x;  s[1] += e * x;
        s[2] += e * c * x;  s[3] += e * d * x;
        s[4] += p * x;      s[5] += x;
        s[6] += c * x;      s[7] += d * x;
    }
}

// ---------------------------------------------------------------------------
// Fused GEMV: grid=148 balanced rows, 8 rows/group, 4 warps/row,
// register double-buffered streaming loads.
// ---------------------------------------------------------------------------
template <int NCOL4, int NROWS_OUT, bool TANH_IN, bool TANH_OUT>
__device__ __forceinline__ void gemv_fused(
    const float* __restrict__ W,
    const float* __restrict__ xin_src,
    const float* __restrict__ act_pre,
    const float* __restrict__ a_pre,
    const float* __restrict__ c_pre,
    const float* __restrict__ d_pre,
    const float* __restrict__ e_pre,
    const float* __restrict__ act_post,
    const float* __restrict__ b_post,
    const float* __restrict__ c_post,
    const float* __restrict__ d_post,
    const float* __restrict__ e_post,
    float* __restrict__ out)
{
    constexpr int Q4 = NCOL4 / 4;          // float4 per quarter-row
    constexpr int NCHUNK = Q4 / 128;       // chunks of 128 float4 per quarter

    __shared__ float4 sx[NCOL4];
    __shared__ float sh[8][32];
    __shared__ float s_sums[8];
    __shared__ float s_heb[64];
    __shared__ float s_part[2][8][4];

    int tid = threadIdx.x;

    // Phase 1: stage x into smem (+tanh for layer 0), Hebbian pre-side sums.
    {
        float s[8] = {0.f, 0.f, 0.f, 0.f, 0.f, 0.f, 0.f, 0.f};
        const float4* x4 = reinterpret_cast<const float4*>(xin_src);
#pragma unroll
        for (int i = tid; i < NCOL4; i += 1024) {
            float4 xv = x4[i];
            if (TANH_IN)
                xv = make_float4(tanhf(xv.x), tanhf(xv.y), tanhf(xv.z), tanhf(xv.w));
            sx[i] = xv;
            float4 actv = reinterpret_cast<const float4*>(act_pre)[i];
            float4 av   = reinterpret_cast<const float4*>(a_pre)[i];
            float4 cv   = reinterpret_cast<const float4*>(c_pre)[i];
            float4 dv   = reinterpret_cast<const float4*>(d_pre)[i];
            float4 ev   = reinterpret_cast<const float4*>(e_pre)[i];
            heb_partial4(s, xv, actv, av, cv, dv, ev);
        }
        block_reduce8(s, sh, s_sums);
    }
    __syncthreads();   // s_sums + sx ready

    // Balanced contiguous row range for this block.
    int r_lo = (int)(((long long)blockIdx.x * NROWS_OUT) / GRID);
    int r_hi = (int)(((long long)(blockIdx.x + 1) * NROWS_OUT) / GRID);
    int nrows = r_hi - r_lo;

    // Precompute Hebbian additive term for all of this block's rows.
    if (tid < nrows) {
        s_heb[tid] = heb_row_val(r_lo + tid, act_post, b_post, c_post, d_post,
                                 e_post, s_sums);
    }
    __syncthreads();

    int warp = tid >> 5;
    int lane = tid & 31;
    int s_slot = warp >> 2;    // 0..7: row slot within group
    int sub = warp & 3;        // 0..3: column quarter

    int ngroups = (nrows + 7) >> 3;
    const float4* Wb = reinterpret_cast<const float4*>(W);

    auto row_of = [&](int g) -> int {
        int r = g * 8 + s_slot;
        return (r < nrows) ? (r_lo + r) : (r_hi - 1);   // clamp (loads only)
    };

    float4 wc[4], wn[4];
    // Prefetch group 0, chunk 0.
    {
        const float4* p = Wb + (size_t)row_of(0) * NCOL4 + sub * Q4 + lane;
#pragma unroll
        for (int u = 0; u < 4; u++) wc[u] = __ldcs(p + u * 32);
    }

    for (int g = 0; g < ngroups; g++) {
        const float4* prow  = Wb + (size_t)row_of(g) * NCOL4 + sub * Q4 + lane;
        int gn = (g + 1 < ngroups) ? (g + 1) : g;
        const float4* pnext = Wb + (size_t)row_of(gn) * NCOL4 + sub * Q4 + lane;

        float4 acc = make_float4(0.f, 0.f, 0.f, 0.f);
#pragma unroll
        for (int k = 0; k < NCHUNK; k++) {
            // Issue next chunk's loads before consuming current chunk.
            const float4* pn = (k + 1 < NCHUNK) ? (prow + (k + 1) * 128) : pnext;
#pragma unroll
            for (int u = 0; u < 4; u++) wn[u] = __ldcs(pn + u * 32);

            int xbase = sub * Q4 + k * 128 + lane;
#pragma unroll
            for (int u = 0; u < 4; u++) {
                float4 xv = sx[xbase + u * 32];
                acc.x = fmaf(wc[u].x, xv.x, acc.x);
                acc.y = fmaf(wc[u].y, xv.y, acc.y);
                acc.z = fmaf(wc[u].z, xv.z, acc.z);
                acc.w = fmaf(wc[u].w, xv.w, acc.w);
            }
#pragma unroll
            for (int u = 0; u < 4; u++) wc[u] = wn[u];
        }

        float part = warp_sum((acc.x + acc.y) + (acc.z + acc.w));
        if (lane == 0) s_part[g & 1][s_slot][sub] = part;
        __syncthreads();

        if (tid < 8) {
            int r = g * 8 + tid;
            if (r < nrows) {
                float v = ((s_part[g & 1][tid][0] + s_part[g & 1][tid][1])
                         + (s_part[g & 1][tid][2] + s_part[g & 1][tid][3]))
                         + s_heb[r];
                out[r_lo + r] = TANH_OUT ? tanhf(v) : v;
            }
        }
        // No second sync: parity double-buffer on s_part makes it safe.
    }
}

// ---------------------------------------------------------------------------
__global__ void __launch_bounds__(1024, 1) k_gemv0(
    const float* __restrict__ W0,
    const float* __restrict__ inputs,
    const float* __restrict__ act0,
    const float* __restrict__ a0,
    const float* __restrict__ c0,
    const float* __restrict__ d0,
    const float* __restrict__ e0,
    const float* __restrict__ act1,
    const float* __restrict__ b1,
    const float* __restrict__ c1,
    const float* __restrict__ d1,
    const float* __restrict__ e1)
{
    gemv_fused<N0 / 4, N1, true, true>(
        W0, inputs, act0, a0, c0, d0, e0,
        act1, b1, c1, d1, e1, g_x1);
}

__global__ void __launch_bounds__(1024, 1) k_gemv1(
    const float* __restrict__ W1,
    const float* __restrict__ act1,
    const float* __restrict__ a1,
    const float* __restrict__ c1,
    const float* __restrict__ d1,
    const float* __restrict__ e1,
    const float* __restrict__ act2,
    const float* __restrict__ b2,
    const float* __restrict__ c2,
    const float* __restrict__ d2,
    const float* __restrict__ e2,
    float* __restrict__ out)
{
    gemv_fused<N1 / 4, N2, false, false>(
        W1, g_x1, act1, a1, c1, d1, e1,
        act2, b2, c2, d2, e2, out);
}

// ---------------------------------------------------------------------------
extern "C" void kernel_launch(void* const* d_in, const int* in_sizes, int n_in,
                              void* d_out, int out_size)
{
    const float* inputs = (const float*)d_in[0];
    const float* act0   = (const float*)d_in[1];
    const float* act1   = (const float*)d_in[2];
    const float* act2   = (const float*)d_in[3];
    const float* W0     = (const float*)d_in[4];
    const float* W1     = (const float*)d_in[5];
    const float* a0     = (const float*)d_in[6];
    const float* c0     = (const float*)d_in[7];
    const float* d0     = (const float*)d_in[8];
    const float* e0     = (const float*)d_in[9];
    const float* a1     = (const float*)d_in[10];
    const float* b1     = (const float*)d_in[11];
    const float* c1     = (const float*)d_in[12];
    const float* d1     = (const float*)d_in[13];
    const float* e1     = (const float*)d_in[14];
    const float* b2     = (const float*)d_in[15];
    const float* c2     = (const float*)d_in[16];
    const float* d2     = (const float*)d_in[17];
    const float* e2     = (const float*)d_in[18];
    float* out = (float*)d_out;

    k_gemv0<<<GRID, 1024>>>(W0, inputs, act0, a0, c0, d0, e0,
                            act1, b1, c1, d1, e1);
    k_gemv1<<<GRID, 1024>>>(W1, act1, a1, c1, d1, e1,
                            act2, b2, c2, d2, e2, out);
}

// round 5
// speedup vs baseline: 1.4049x; 1.1103x over previous
#include <cuda_runtime.h>
#include <cstdint>

#define N0 4096
#define N1 8192
#define N2 4096
#define GRID 148

// Scratch (allocation-free: __device__ global)
__device__ __align__(16) float g_x1[N1];

__device__ __forceinline__ float warp_sum(float v) {
#pragma unroll
    for (int o = 16; o > 0; o >>= 1) v += __shfl_xor_sync(0xffffffffu, v, o);
    return v;
}

__device__ __forceinline__ uint32_t smem_u32(const void* p) {
    return (uint32_t)__cvta_generic_to_shared(p);
}
__device__ __forceinline__ void cp_async16(uint32_t dst, const void* src) {
    asm volatile("cp.async.cg.shared.global [%0], [%1], 16;" :: "r"(dst), "l"(src));
}
#define CP_COMMIT() asm volatile("cp.async.commit_group;" ::: "memory")
#define CP_WAIT(n)  asm volatile("cp.async.wait_group %0;" :: "n"(n) : "memory")

// Block-wide reduction of 8 partial sums (1024 threads). Deterministic.
__device__ __forceinline__ void block_reduce8(float s[8], float (*sh)[32], float* s_sums)
{
    int tid = threadIdx.x;
    int w = tid >> 5, l = tid & 31;
#pragma unroll
    for (int k = 0; k < 8; k++) s[k] = warp_sum(s[k]);
    if (l == 0) {
#pragma unroll
        for (int k = 0; k < 8; k++) sh[k][w] = s[k];
    }
    __syncthreads();
    if (tid < 256) {
        int k = tid >> 5, ln = tid & 31;
        float v = warp_sum(sh[k][ln]);
        if (ln == 0) s_sums[k] = v;
    }
}

__device__ __forceinline__ float heb_row_val(
    int row,
    const float* __restrict__ act_post,
    const float* __restrict__ b_post,
    const float* __restrict__ c_post,
    const float* __restrict__ d_post,
    const float* __restrict__ e_post,
    const float* __restrict__ sums)
{
    float P = b_post[row] * act_post[row];
    float C = c_post[row] * act_post[row];
    float D = d_post[row];
    float E = e_post[row];
    return 0.5f * (sums[0] + P * sums[1] + C * sums[2] + D * sums[3]
          + E * (sums[4] + P * sums[5] + C * sums[6] + D * sums[7]));
}

__device__ __forceinline__ void heb_partial4(
    float s[8], float4 xv, float4 actv, float4 av, float4 cv, float4 dv, float4 ev)
{
    float xs[4]  = {xv.x, xv.y, xv.z, xv.w};
    float acs[4] = {actv.x, actv.y, actv.z, actv.w};
    float as[4]  = {av.x, av.y, av.z, av.w};
    float cs[4]  = {cv.x, cv.y, cv.z, cv.w};
    float ds[4]  = {dv.x, dv.y, dv.z, dv.w};
    float es[4]  = {ev.x, ev.y, ev.z, ev.w};
#pragma unroll
    for (int j = 0; j < 4; j++) {
        float x = xs[j], e = es[j];
        float p = as[j] * acs[j];
        float c = cs[j] * acs[j];
        float d = ds[j];
        s[0] += e * p * x;  s[1] += e * x;
        s[2] += e * c * x;  s[3] += e * d * x;
        s[4] += p * x;      s[5] += x;
        s[6] += c * x;      s[7] += d * x;
    }
}

// ---------------------------------------------------------------------------
// Fused GEMV: cp.async row pipeline (NBUF rows deep), x in registers,
// thread t owns columns [16t, 16t+16) bytes -> no block sync on data path.
// ---------------------------------------------------------------------------
template <int NCOL4, int NROWS_OUT, bool TANH_IN, bool TANH_OUT, int NBUF>
__device__ __forceinline__ void gemv_fused(
    const float* __restrict__ W,
    const float* __restrict__ xin_src,
    const float* __restrict__ act_pre,
    const float* __restrict__ a_pre,
    const float* __restrict__ c_pre,
    const float* __restrict__ d_pre,
    const float* __restrict__ e_pre,
    const float* __restrict__ act_post,
    const float* __restrict__ b_post,
    const float* __restrict__ c_post,
    const float* __restrict__ d_post,
    const float* __restrict__ e_post,
    float* __restrict__ out)
{
    constexpr int F4PT = NCOL4 / 1024;   // float4 per thread per row (1 or 2)

    extern __shared__ float4 dynbuf[];   // NBUF * NCOL4 float4
    __shared__ float sh[8][32];
    __shared__ float s_sums[8];
    __shared__ float s_heb[64];
    __shared__ float s_part[2][8][32];

    int tid = threadIdx.x;
    int lane = tid & 31;
    int warp = tid >> 5;

    int r_lo = (int)(((long long)blockIdx.x * NROWS_OUT) / GRID);
    int r_hi = (int)(((long long)(blockIdx.x + 1) * NROWS_OUT) / GRID);
    int nrows = r_hi - r_lo;

    const float4* Wb = reinterpret_cast<const float4*>(W) + (size_t)r_lo * NCOL4;
    uint32_t sbase = smem_u32(dynbuf);

    // Kick off DRAM immediately: prefetch first NBUF rows.
#pragma unroll
    for (int r = 0; r < NBUF; r++) {
        if (r < nrows) {
#pragma unroll
            for (int j = 0; j < F4PT; j++) {
                int col = tid + j * 1024;
                cp_async16(sbase + (uint32_t)((r % NBUF) * NCOL4 + col) * 16u,
                           Wb + (size_t)r * NCOL4 + col);
            }
        }
        CP_COMMIT();
    }

    // x into registers (+tanh), Hebbian pre-side sums (overlaps prefetch).
    float4 xr[F4PT];
    {
        float s[8] = {0.f, 0.f, 0.f, 0.f, 0.f, 0.f, 0.f, 0.f};
#pragma unroll
        for (int j = 0; j < F4PT; j++) {
            int i = tid + j * 1024;
            float4 xv = reinterpret_cast<const float4*>(xin_src)[i];
            if (TANH_IN)
                xv = make_float4(tanhf(xv.x), tanhf(xv.y), tanhf(xv.z), tanhf(xv.w));
            xr[j] = xv;
            float4 actv = reinterpret_cast<const float4*>(act_pre)[i];
            float4 av   = reinterpret_cast<const float4*>(a_pre)[i];
            float4 cv   = reinterpret_cast<const float4*>(c_pre)[i];
            float4 dv   = reinterpret_cast<const float4*>(d_pre)[i];
            float4 ev   = reinterpret_cast<const float4*>(e_pre)[i];
            heb_partial4(s, xv, actv, av, cv, dv, ev);
        }
        block_reduce8(s, sh, s_sums);
    }
    __syncthreads();
    if (tid < nrows) {
        s_heb[tid] = heb_row_val(r_lo + tid, act_post, b_post, c_post, d_post,
                                 e_post, s_sums);
    }
    __syncthreads();

    // Mainloop: one row at a time, whole block cooperates. cp.async groups are
    // per-thread and each thread reads only what it copied, so wait_group is
    // the only ordering needed for the data.
    int par = 0;
    for (int r = 0; r < nrows; r++) {
        CP_WAIT(NBUF - 1);

        const float4* buf = dynbuf + (r % NBUF) * NCOL4;
        float4 wv[F4PT];
#pragma unroll
        for (int j = 0; j < F4PT; j++) wv[j] = buf[tid + j * 1024];

        float acc = 0.f;
#pragma unroll
        for (int j = 0; j < F4PT; j++) {
            acc = fmaf(wv[j].x, xr[j].x, acc);
            acc = fmaf(wv[j].y, xr[j].y, acc);
            acc = fmaf(wv[j].z, xr[j].z, acc);
            acc = fmaf(wv[j].w, xr[j].w, acc);
        }
        float p = warp_sum(acc);
        if (lane == 0) s_part[par][r & 7][warp] = p;

        // Prefetch row r+NBUF (empty commit at tail keeps group cadence).
        int rp = r + NBUF;
        if (rp < nrows) {
#pragma unroll
            for (int j = 0; j < F4PT; j++) {
                int col = tid + j * 1024;
                cp_async16(sbase + (uint32_t)((rp % NBUF) * NCOL4 + col) * 16u,
                           Wb + (size_t)rp * NCOL4 + col);
            }
        }
        CP_COMMIT();

        if ((r & 7) == 7 || r == nrows - 1) {
            __syncthreads();
            if (tid < 256) {
                int rr = (r & ~7) + warp;     // warp = 0..7 here
                if (rr < nrows) {
                    float v = warp_sum(s_part[par][warp][lane]);
                    if (lane == 0) {
                        float y = v + s_heb[rr];
                        out[r_lo + rr] = TANH_OUT ? tanhf(y) : y;
                    }
                }
            }
            par ^= 1;
            // next group writes the other parity; parity `par` is not written
            // again until after the next boundary sync -> safe with one sync.
        }
    }
}

// ---------------------------------------------------------------------------
__global__ void __launch_bounds__(1024, 1) k_gemv0(
    const float* __restrict__ W0,
    const float* __restrict__ inputs,
    const float* __restrict__ act0,
    const float* __restrict__ a0,
    const float* __restrict__ c0,
    const float* __restrict__ d0,
    const float* __restrict__ e0,
    const float* __restrict__ act1,
    const float* __restrict__ b1,
    const float* __restrict__ c1,
    const float* __restrict__ d1,
    const float* __restrict__ e1)
{
    gemv_fused<N0 / 4, N1, true, true, 8>(
        W0, inputs, act0, a0, c0, d0, e0,
        act1, b1, c1, d1, e1, g_x1);
}

__global__ void __launch_bounds__(1024, 1) k_gemv1(
    const float* __restrict__ W1,
    const float* __restrict__ act1,
    const float* __restrict__ a1,
    const float* __restrict__ c1,
    const float* __restrict__ d1,
    const float* __restrict__ e1,
    const float* __restrict__ act2,
    const float* __restrict__ b2,
    const float* __restrict__ c2,
    const float* __restrict__ d2,
    const float* __restrict__ e2,
    float* __restrict__ out)
{
    gemv_fused<N1 / 4, N2, false, false, 4>(
        W1, g_x1, act1, a1, c1, d1, e1,
        act2, b2, c2, d2, e2, out);
}

// ---------------------------------------------------------------------------
extern "C" void kernel_launch(void* const* d_in, const int* in_sizes, int n_in,
                              void* d_out, int out_size)
{
    const float* inputs = (const float*)d_in[0];
    const float* act0   = (const float*)d_in[1];
    const float* act1   = (const float*)d_in[2];
    const float* act2   = (const float*)d_in[3];
    const float* W0     = (const float*)d_in[4];
    const float* W1     = (const float*)d_in[5];
    const float* a0     = (const float*)d_in[6];
    const float* c0     = (const float*)d_in[7];
    const float* d0     = (const float*)d_in[8];
    const float* e0     = (const float*)d_in[9];
    const float* a1     = (const float*)d_in[10];
    const float* b1     = (const float*)d_in[11];
    const float* c1     = (const float*)d_in[12];
    const float* d1     = (const float*)d_in[13];
    const float* e1     = (const float*)d_in[14];
    const float* b2     = (const float*)d_in[15];
    const float* c2     = (const float*)d_in[16];
    const float* d2     = (const float*)d_in[17];
    const float* e2     = (const float*)d_in[18];
    float* out = (float*)d_out;

    // 8 buffers * 1024 float4 (gemv0) == 4 buffers * 2048 float4 (gemv1) == 128 KB
    const int SMEM_DYN = 8 * (N0 / 4) * (int)sizeof(float4);
    cudaFuncSetAttribute(k_gemv0, cudaFuncAttributeMaxDynamicSharedMemorySize, SMEM_DYN);
    cudaFuncSetAttribute(k_gemv1, cudaFuncAttributeMaxDynamicSharedMemorySize, SMEM_DYN);

    k_gemv0<<<GRID, 1024, SMEM_DYN>>>(W0, inputs, act0, a0, c0, d0, e0,
                                      act1, b1, c1, d1, e1);
    k_gemv1<<<GRID, 1024, SMEM_DYN>>>(W1, act1, a1, c1, d1, e1,
                                      act2, b2, c2, d2, e2, out);
}